// round 4
// baseline (speedup 1.0000x reference)
#include <cuda_runtime.h>
#include <cuda_fp16.h>

#define NN 100000
#define NE 1000000
#define D  64
#define HS 68              // smem h-row stride (floats)
#define SCAN_BS 1024
#define NBLK 98            // ceil(NN/1024)

// ---------------- static scratch ----------------
__device__ __half2 g_bufA[NN * (D / 2)];   // fp16 feature buffer (ping)
__device__ __half2 g_bufB[NN * (D / 2)];   // fp16 feature buffer (pong)
__device__ float g_out_norm[NN];
__device__ float g_in_norm[NN];
__device__ int   g_deg_out[NN];
__device__ int   g_deg_in[NN];
__device__ int   g_row_start[NN];
__device__ int   g_fill[NN];
__device__ int   g_src_sorted[NE];
__device__ int   g_bsum[NBLK];
__device__ int   g_boff[NBLK];

// ---------------- f32x2 helpers ----------------
__device__ __forceinline__ unsigned long long pk2(float lo, float hi) {
    unsigned long long r;
    asm("mov.b64 %0, {%1,%2};" : "=l"(r) : "f"(lo), "f"(hi));
    return r;
}
__device__ __forceinline__ void fma2(unsigned long long& d,
                                     unsigned long long a, unsigned long long b) {
    asm("fma.rn.f32x2 %0, %1, %2, %0;" : "+l"(d) : "l"(a), "l"(b));
}
__device__ __forceinline__ float2 upk2(unsigned long long v) {
    float2 f;
    asm("mov.b64 {%0,%1}, %2;" : "=f"(f.x), "=f"(f.y) : "l"(v));
    return f;
}

// ---------------- setup kernels ----------------
__global__ void zero_deg_kernel() {
    int i = blockIdx.x * blockDim.x + threadIdx.x;
    if (i < NN) { g_deg_out[i] = 0; g_deg_in[i] = 0; }
}

__global__ void count_kernel(const int* __restrict__ src, const int* __restrict__ dst) {
    int e = blockIdx.x * blockDim.x + threadIdx.x;
    if (e < NE) {
        atomicAdd(&g_deg_out[src[e]], 1);
        atomicAdd(&g_deg_in[dst[e]], 1);
    }
}

// block-level scan of deg_in
__global__ void scan1_kernel() {
    __shared__ int sh[SCAN_BS];
    int t = threadIdx.x;
    int i = blockIdx.x * SCAN_BS + t;
    int v = (i < NN) ? g_deg_in[i] : 0;
    sh[t] = v;
    __syncthreads();
#pragma unroll
    for (int off = 1; off < SCAN_BS; off <<= 1) {
        int xv = (t >= off) ? sh[t - off] : 0;
        __syncthreads();
        sh[t] += xv;
        __syncthreads();
    }
    if (i < NN) g_row_start[i] = sh[t] - v;   // exclusive within block
    if (t == SCAN_BS - 1) g_bsum[blockIdx.x] = sh[t];
}

// parallel scan of the 98 block sums
__global__ void scan2_kernel() {
    __shared__ int s[128];
    int t = threadIdx.x;
    int v = (t < NBLK) ? g_bsum[t] : 0;
    s[t] = v;
    __syncthreads();
#pragma unroll
    for (int off = 1; off < 128; off <<= 1) {
        int xv = (t >= off) ? s[t - off] : 0;
        __syncthreads();
        s[t] += xv;
        __syncthreads();
    }
    if (t < NBLK) g_boff[t] = s[t] - v;       // exclusive
}

// finalize row offsets + fill cursors + degree norms (fused)
__global__ void scan3_kernel() {
    int i = blockIdx.x * blockDim.x + threadIdx.x;
    if (i < NN) {
        int rs = g_row_start[i] + g_boff[i >> 10];
        g_row_start[i] = rs;
        g_fill[i] = rs;
        int dout = g_deg_out[i]; if (dout < 1) dout = 1;
        int din  = g_deg_in[i];  if (din  < 1) din  = 1;
        g_out_norm[i] = rsqrtf((float)dout);
        g_in_norm[i]  = rsqrtf((float)din);
    }
}

__global__ void fill_kernel(const int* __restrict__ src, const int* __restrict__ dst) {
    int e = blockIdx.x * blockDim.x + threadIdx.x;
    if (e < NE) {
        int p = atomicAdd(&g_fill[dst[e]], 1);
        g_src_sorted[p] = src[e];
    }
}

// xs = fp16( x * out_norm[row] ) into bufA. One thread = 4 floats -> 2 half2.
__global__ void prescale_kernel(const float4* __restrict__ x) {
    int i = blockIdx.x * blockDim.x + threadIdx.x;
    if (i < NN * (D / 4)) {
        float s = g_out_norm[i >> 4];
        float4 v = __ldg(&x[i]);
        g_bufA[i * 2]     = __floats2half2_rn(v.x * s, v.y * s);
        g_bufA[i * 2 + 1] = __floats2half2_rn(v.z * s, v.w * s);
    }
}

// ---------------- fused gather + GEMM layer ----------------
// in_sel: 0 = bufA, 1 = bufB.  out_ext != nullptr -> fp32 external output,
// else fp16 output to (out_sel ? bufB : bufA).  Buffer addresses taken in
// DEVICE code (passing __device__ symbols from host is UB — R3 bug).
__global__ void __launch_bounds__(256) layer_kernel(
        int in_sel, float* __restrict__ out_ext, int out_sel,
        const float* __restrict__ W, const float* __restrict__ b,
        int relu, int scale_out) {
    __shared__ float sW[D * D];     // 16KB
    __shared__ float sh[16 * HS];
    __shared__ float sb[D];

    int tid = threadIdx.x;
    for (int i = tid; i < D * D; i += 256) sW[i] = W[i];
    if (tid < D) sb[tid] = b[tid];

    const __half2* in = in_sel ? g_bufB : g_bufA;
    __half2* out_h16 = out_sel ? g_bufB : g_bufA;

    // ---- phase 1: aggregation (fp16 rows, fp32 accumulate) ----
    int g = tid >> 4, c = tid & 15;
    int node = blockIdx.x * 16 + g;
    float4 acc = make_float4(0.f, 0.f, 0.f, 0.f);
    if (node < NN) {
        const uint2* inp = reinterpret_cast<const uint2*>(in);  // 8B = 4 halves
        int e = g_row_start[node];
        int eend = e + g_deg_in[node];
        for (; e + 3 < eend; e += 4) {
            int s0 = g_src_sorted[e],     s1 = g_src_sorted[e + 1];
            int s2 = g_src_sorted[e + 2], s3 = g_src_sorted[e + 3];
            uint2 r0 = __ldg(&inp[s0 * 16 + c]);
            uint2 r1 = __ldg(&inp[s1 * 16 + c]);
            uint2 r2 = __ldg(&inp[s2 * 16 + c]);
            uint2 r3 = __ldg(&inp[s3 * 16 + c]);
#pragma unroll
            for (int q = 0; q < 4; q++) {
                uint2 r = (q == 0) ? r0 : (q == 1) ? r1 : (q == 2) ? r2 : r3;
                float2 f0 = __half22float2(*reinterpret_cast<__half2*>(&r.x));
                float2 f1 = __half22float2(*reinterpret_cast<__half2*>(&r.y));
                acc.x += f0.x; acc.y += f0.y; acc.z += f1.x; acc.w += f1.y;
            }
        }
        for (; e < eend; e++) {
            int s0 = g_src_sorted[e];
            uint2 r = __ldg(&inp[s0 * 16 + c]);
            float2 f0 = __half22float2(*reinterpret_cast<__half2*>(&r.x));
            float2 f1 = __half22float2(*reinterpret_cast<__half2*>(&r.y));
            acc.x += f0.x; acc.y += f0.y; acc.z += f1.x; acc.w += f1.y;
        }
        float nrm = g_in_norm[node];
        acc.x *= nrm; acc.y *= nrm; acc.z *= nrm; acc.w *= nrm;
    }
    *reinterpret_cast<float4*>(&sh[g * HS + c * 4]) = acc;
    __syncthreads();

    // ---- phase 2: GEMM (warps 0,1; 8 nodes each, FFMA2) ----
    int w = tid >> 5;
    if (w < 2) {
        int lane = tid & 31;
        int r0 = lane >> 4;       // 0/1
        int c2 = lane & 15;       // output col quad
        unsigned long long acc01[4], acc23[4];
#pragma unroll
        for (int m = 0; m < 4; m++) { acc01[m] = 0ull; acc23[m] = 0ull; }

#pragma unroll
        for (int kb = 0; kb < 16; kb++) {
            float4 a4[4];
#pragma unroll
            for (int m = 0; m < 4; m++)
                a4[m] = *reinterpret_cast<const float4*>(
                    &sh[(w * 8 + r0 + 2 * m) * HS + kb * 4]);
#pragma unroll
            for (int q = 0; q < 4; q++) {
                int k = kb * 4 + q;
                unsigned long long w01 =
                    *reinterpret_cast<const unsigned long long*>(&sW[k * D + c2 * 4]);
                unsigned long long w23 =
                    *reinterpret_cast<const unsigned long long*>(&sW[k * D + c2 * 4 + 2]);
#pragma unroll
                for (int m = 0; m < 4; m++) {
                    float a = (q == 0) ? a4[m].x : (q == 1) ? a4[m].y
                             : (q == 2) ? a4[m].z : a4[m].w;
                    unsigned long long aa = pk2(a, a);
                    fma2(acc01[m], aa, w01);
                    fma2(acc23[m], aa, w23);
                }
            }
        }
        // epilogue
        float b0 = sb[c2 * 4 + 0], b1 = sb[c2 * 4 + 1];
        float b2 = sb[c2 * 4 + 2], b3 = sb[c2 * 4 + 3];
#pragma unroll
        for (int m = 0; m < 4; m++) {
            int nd = blockIdx.x * 16 + w * 8 + r0 + 2 * m;
            if (nd < NN) {
                float2 v01 = upk2(acc01[m]);
                float2 v23 = upk2(acc23[m]);
                float o0 = v01.x + b0, o1 = v01.y + b1;
                float o2 = v23.x + b2, o3 = v23.y + b3;
                if (relu) {
                    o0 = fmaxf(o0, 0.f); o1 = fmaxf(o1, 0.f);
                    o2 = fmaxf(o2, 0.f); o3 = fmaxf(o3, 0.f);
                }
                if (scale_out) {
                    float on = g_out_norm[nd];
                    o0 *= on; o1 *= on; o2 *= on; o3 *= on;
                }
                if (out_ext) {
                    reinterpret_cast<float4*>(out_ext)[nd * 16 + c2] =
                        make_float4(o0, o1, o2, o3);
                } else {
                    out_h16[(nd * 32) + c2 * 2]     = __floats2half2_rn(o0, o1);
                    out_h16[(nd * 32) + c2 * 2 + 1] = __floats2half2_rn(o2, o3);
                }
            }
        }
    }
}

// ---------------- launch ----------------
extern "C" void kernel_launch(void* const* d_in, const int* in_sizes, int n_in,
                              void* d_out, int out_size) {
    const float* x   = (const float*)d_in[0];
    const int*   src = (const int*)d_in[1];
    const int*   dst = (const int*)d_in[2];
    const float* W1  = (const float*)d_in[3];
    const float* b1  = (const float*)d_in[4];
    const float* W2  = (const float*)d_in[5];
    const float* b2  = (const float*)d_in[6];
    const float* W3  = (const float*)d_in[7];
    const float* b3  = (const float*)d_in[8];
    float* out = (float*)d_out;

    const int TB = 256;
    const int GN = (NN + TB - 1) / TB;
    const int GE = (NE + TB - 1) / TB;

    zero_deg_kernel<<<GN, TB>>>();
    count_kernel<<<GE, TB>>>(src, dst);
    scan1_kernel<<<NBLK, SCAN_BS>>>();
    scan2_kernel<<<1, 128>>>();
    scan3_kernel<<<GN, TB>>>();           // also computes norms + fill cursors
    fill_kernel<<<GE, TB>>>(src, dst);
    prescale_kernel<<<(NN * 16 + TB - 1) / TB, TB>>>(
        reinterpret_cast<const float4*>(x));

    const int GL = (NN + 15) / 16;
    // layer 1: bufA(xs,fp16) -> bufB(fp16), relu, fold next-layer out_norm
    layer_kernel<<<GL, 256>>>(0, nullptr, 1, W1, b1, 1, 1);
    // layer 2: bufB -> bufA, relu, fold out_norm
    layer_kernel<<<GL, 256>>>(1, nullptr, 0, W2, b2, 1, 1);
    // layer 3: bufA -> d_out (fp32), no relu, no scale
    layer_kernel<<<GL, 256>>>(0, out, 0, W3, b3, 0, 0);
}

// round 6
// speedup vs baseline: 1.4970x; 1.4970x over previous
#include <cuda_runtime.h>
#include <cuda_fp16.h>

#define NN 100000
#define NE 1000000
#define D  64
#define HS 68              // smem h-row stride (floats)
#define SCAN_BS 1024
#define NBLK 98            // ceil(NN/1024)

// ---------------- static scratch ----------------
__device__ __half2 g_bufA[NN * (D / 2)];   // fp16 feature buffer (ping)
__device__ __half2 g_bufB[NN * (D / 2)];   // fp16 feature buffer (pong)
__device__ float g_out_norm[NN];
__device__ float g_in_norm[NN];
__device__ int   g_deg_out[NN];
__device__ int   g_deg_in[NN];
__device__ int   g_row_start[NN];
__device__ int   g_fill[NN];
__device__ int   g_src_sorted[NE];
__device__ int   g_bsum[NBLK];
__device__ int   g_boff[NBLK];

// ---------------- helpers ----------------
__device__ __forceinline__ unsigned long long pk2(float lo, float hi) {
    unsigned long long r;
    asm("mov.b64 %0, {%1,%2};" : "=l"(r) : "f"(lo), "f"(hi));
    return r;
}
__device__ __forceinline__ void fma2(unsigned long long& d,
                                     unsigned long long a, unsigned long long b) {
    asm("fma.rn.f32x2 %0, %1, %2, %0;" : "+l"(d) : "l"(a), "l"(b));
}
__device__ __forceinline__ float2 upk2(unsigned long long v) {
    float2 f;
    asm("mov.b64 {%0,%1}, %2;" : "=f"(f.x), "=f"(f.y) : "l"(v));
    return f;
}
// half2-bits (uint) -> float2; pure register conversion via PTX
__device__ __forceinline__ float2 h2f(unsigned int u) {
    float2 f;
    asm("{\n\t"
        ".reg .f16 lo, hi;\n\t"
        "mov.b32 {lo, hi}, %2;\n\t"
        "cvt.f32.f16 %0, lo;\n\t"
        "cvt.f32.f16 %1, hi;\n\t"
        "}"
        : "=f"(f.x), "=f"(f.y) : "r"(u));
    return f;
}
__device__ __forceinline__ unsigned int f2h(float a, float b) {
    unsigned int u;
    asm("{\n\t"
        ".reg .f16 lo, hi;\n\t"
        "cvt.rn.f16.f32 lo, %1;\n\t"
        "cvt.rn.f16.f32 hi, %2;\n\t"
        "mov.b32 %0, {lo, hi};\n\t"
        "}"
        : "=r"(u) : "f"(a), "f"(b));
    return u;
}
// accumulate one 16B chunk (8 halves) into 8 fp32 accumulators
__device__ __forceinline__ void addrow(float* acc, uint4 r) {
    float2 f;
    f = h2f(r.x); acc[0] += f.x; acc[1] += f.y;
    f = h2f(r.y); acc[2] += f.x; acc[3] += f.y;
    f = h2f(r.z); acc[4] += f.x; acc[5] += f.y;
    f = h2f(r.w); acc[6] += f.x; acc[7] += f.y;
}

// ---------------- setup kernels ----------------
__global__ void zero_deg_kernel() {
    int i = blockIdx.x * blockDim.x + threadIdx.x;
    if (i < NN) { g_deg_out[i] = 0; g_deg_in[i] = 0; }
}

__global__ void count_kernel(const int* __restrict__ src, const int* __restrict__ dst) {
    int e = blockIdx.x * blockDim.x + threadIdx.x;
    if (e < NE) {
        atomicAdd(&g_deg_out[src[e]], 1);
        atomicAdd(&g_deg_in[dst[e]], 1);
    }
}

// block-level scan of deg_in
__global__ void scan1_kernel() {
    __shared__ int sh[SCAN_BS];
    int t = threadIdx.x;
    int i = blockIdx.x * SCAN_BS + t;
    int v = (i < NN) ? g_deg_in[i] : 0;
    sh[t] = v;
    __syncthreads();
#pragma unroll
    for (int off = 1; off < SCAN_BS; off <<= 1) {
        int xv = (t >= off) ? sh[t - off] : 0;
        __syncthreads();
        sh[t] += xv;
        __syncthreads();
    }
    if (i < NN) g_row_start[i] = sh[t] - v;
    if (t == SCAN_BS - 1) g_bsum[blockIdx.x] = sh[t];
}

__global__ void scan2_kernel() {
    __shared__ int s[128];
    int t = threadIdx.x;
    int v = (t < NBLK) ? g_bsum[t] : 0;
    s[t] = v;
    __syncthreads();
#pragma unroll
    for (int off = 1; off < 128; off <<= 1) {
        int xv = (t >= off) ? s[t - off] : 0;
        __syncthreads();
        s[t] += xv;
        __syncthreads();
    }
    if (t < NBLK) g_boff[t] = s[t] - v;
}

// finalize row offsets + fill cursors + degree norms
__global__ void scan3_kernel() {
    int i = blockIdx.x * blockDim.x + threadIdx.x;
    if (i < NN) {
        int rs = g_row_start[i] + g_boff[i >> 10];
        g_row_start[i] = rs;
        g_fill[i] = rs;
        int dout = g_deg_out[i]; if (dout < 1) dout = 1;
        int din  = g_deg_in[i];  if (din  < 1) din  = 1;
        g_out_norm[i] = rsqrtf((float)dout);
        g_in_norm[i]  = rsqrtf((float)din);
    }
}

__global__ void fill_kernel(const int* __restrict__ src, const int* __restrict__ dst) {
    int e = blockIdx.x * blockDim.x + threadIdx.x;
    if (e < NE) {
        int p = atomicAdd(&g_fill[dst[e]], 1);
        g_src_sorted[p] = src[e];
    }
}

// xs = fp16( x * out_norm[row] ) into bufA; one 8B store per thread
__global__ void prescale_kernel(const float4* __restrict__ x) {
    int i = blockIdx.x * blockDim.x + threadIdx.x;
    if (i < NN * (D / 4)) {
        float s = g_out_norm[i >> 4];
        float4 v = __ldg(&x[i]);
        uint2 st;
        st.x = f2h(v.x * s, v.y * s);
        st.y = f2h(v.z * s, v.w * s);
        reinterpret_cast<uint2*>(g_bufA)[i] = st;
    }
}

// ---------------- fused gather + GEMM layer ----------------
// Phase 1: per node, 16 lanes = 2 octets; each octet streams alternate in-edges,
//          each lane loads 16B (uint4, LDG.128) of the fp16 row, fp32 accumulate,
//          octets merged by shfl_xor(8).  Phase 2: warps 0-1 GEMM (FFMA2).
__global__ void __launch_bounds__(256) layer_kernel(
        int in_sel, float* __restrict__ out_ext, int out_sel,
        const float* __restrict__ W, const float* __restrict__ b,
        int relu, int scale_out) {
    __shared__ float sW[D * D];
    __shared__ float sh[16 * HS];
    __shared__ float sb[D];

    int tid = threadIdx.x;
    for (int i = tid; i < D * D; i += 256) sW[i] = W[i];
    if (tid < D) sb[tid] = b[tid];

    const __half2* in = in_sel ? g_bufB : g_bufA;
    __half2* out_h16 = out_sel ? g_bufB : g_bufA;

    // ---- phase 1: aggregation ----
    int g   = tid >> 4;         // node slot 0..15
    int sub = (tid >> 3) & 1;   // octet 0/1
    int c8  = tid & 7;          // 16B column slice
    int node = blockIdx.x * 16 + g;

    float acc[8];
#pragma unroll
    for (int j = 0; j < 8; j++) acc[j] = 0.f;

    if (node < NN) {
        const uint4* inp = reinterpret_cast<const uint4*>(in);  // 8 uint4 per row
        int rbeg = g_row_start[node];
        int eend = rbeg + g_deg_in[node];
        int e = rbeg + sub;                 // octet handles edges rbeg+sub, +2, ...
        for (; e + 2 < eend; e += 4) {
            int s0 = g_src_sorted[e];
            int s1 = g_src_sorted[e + 2];
            uint4 r0 = __ldg(&inp[s0 * 8 + c8]);
            uint4 r1 = __ldg(&inp[s1 * 8 + c8]);
            addrow(acc, r0);
            addrow(acc, r1);
        }
        if (e < eend) {
            int s0 = g_src_sorted[e];
            uint4 r0 = __ldg(&inp[s0 * 8 + c8]);
            addrow(acc, r0);
        }
    }
    // merge octets (lane L and L^8 hold the same columns)
#pragma unroll
    for (int j = 0; j < 8; j++)
        acc[j] += __shfl_xor_sync(0xffffffffu, acc[j], 8);

    if (node < NN && sub == 0) {
        float nrm = g_in_norm[node];
        float* dstp = &sh[g * HS + c8 * 8];
        *reinterpret_cast<float4*>(dstp) =
            make_float4(acc[0] * nrm, acc[1] * nrm, acc[2] * nrm, acc[3] * nrm);
        *reinterpret_cast<float4*>(dstp + 4) =
            make_float4(acc[4] * nrm, acc[5] * nrm, acc[6] * nrm, acc[7] * nrm);
    }
    __syncthreads();

    // ---- phase 2: GEMM (warps 0,1; 8 nodes each, FFMA2) ----
    int w = tid >> 5;
    if (w < 2) {
        int lane = tid & 31;
        int r0 = lane >> 4;       // 0/1
        int c2 = lane & 15;       // output col quad
        unsigned long long acc01[4], acc23[4];
#pragma unroll
        for (int m = 0; m < 4; m++) { acc01[m] = 0ull; acc23[m] = 0ull; }

#pragma unroll
        for (int kb = 0; kb < 16; kb++) {
            float4 a4[4];
#pragma unroll
            for (int m = 0; m < 4; m++)
                a4[m] = *reinterpret_cast<const float4*>(
                    &sh[(w * 8 + r0 + 2 * m) * HS + kb * 4]);
#pragma unroll
            for (int q = 0; q < 4; q++) {
                int k = kb * 4 + q;
                unsigned long long w01 =
                    *reinterpret_cast<const unsigned long long*>(&sW[k * D + c2 * 4]);
                unsigned long long w23 =
                    *reinterpret_cast<const unsigned long long*>(&sW[k * D + c2 * 4 + 2]);
#pragma unroll
                for (int m = 0; m < 4; m++) {
                    float a = (q == 0) ? a4[m].x : (q == 1) ? a4[m].y
                             : (q == 2) ? a4[m].z : a4[m].w;
                    unsigned long long aa = pk2(a, a);
                    fma2(acc01[m], aa, w01);
                    fma2(acc23[m], aa, w23);
                }
            }
        }
        float b0 = sb[c2 * 4 + 0], b1 = sb[c2 * 4 + 1];
        float b2 = sb[c2 * 4 + 2], b3 = sb[c2 * 4 + 3];
#pragma unroll
        for (int m = 0; m < 4; m++) {
            int nd = blockIdx.x * 16 + w * 8 + r0 + 2 * m;
            if (nd < NN) {
                float2 v01 = upk2(acc01[m]);
                float2 v23 = upk2(acc23[m]);
                float o0 = v01.x + b0, o1 = v01.y + b1;
                float o2 = v23.x + b2, o3 = v23.y + b3;
                if (relu) {
                    o0 = fmaxf(o0, 0.f); o1 = fmaxf(o1, 0.f);
                    o2 = fmaxf(o2, 0.f); o3 = fmaxf(o3, 0.f);
                }
                if (scale_out) {
                    float on = g_out_norm[nd];
                    o0 *= on; o1 *= on; o2 *= on; o3 *= on;
                }
                if (out_ext) {
                    reinterpret_cast<float4*>(out_ext)[nd * 16 + c2] =
                        make_float4(o0, o1, o2, o3);
                } else {
                    uint2 st;
                    st.x = f2h(o0, o1);
                    st.y = f2h(o2, o3);
                    reinterpret_cast<uint2*>(out_h16)[nd * 16 + c2] = st;
                }
            }
        }
    }
}

// ---------------- launch ----------------
extern "C" void kernel_launch(void* const* d_in, const int* in_sizes, int n_in,
                              void* d_out, int out_size) {
    const float* x   = (const float*)d_in[0];
    const int*   src = (const int*)d_in[1];
    const int*   dst = (const int*)d_in[2];
    const float* W1  = (const float*)d_in[3];
    const float* b1  = (const float*)d_in[4];
    const float* W2  = (const float*)d_in[5];
    const float* b2  = (const float*)d_in[6];
    const float* W3  = (const float*)d_in[7];
    const float* b3  = (const float*)d_in[8];
    float* out = (float*)d_out;

    const int TB = 256;
    const int GN = (NN + TB - 1) / TB;
    const int GE = (NE + TB - 1) / TB;

    zero_deg_kernel<<<GN, TB>>>();
    count_kernel<<<GE, TB>>>(src, dst);
    scan1_kernel<<<NBLK, SCAN_BS>>>();
    scan2_kernel<<<1, 128>>>();
    scan3_kernel<<<GN, TB>>>();
    fill_kernel<<<GE, TB>>>(src, dst);
    prescale_kernel<<<(NN * 16 + TB - 1) / TB, TB>>>(
        reinterpret_cast<const float4*>(x));

    const int GL = (NN + 15) / 16;
    layer_kernel<<<GL, 256>>>(0, nullptr, 1, W1, b1, 1, 1);   // bufA -> bufB
    layer_kernel<<<GL, 256>>>(1, nullptr, 0, W2, b2, 1, 1);   // bufB -> bufA
    layer_kernel<<<GL, 256>>>(0, out, 0, W3, b3, 0, 0);       // bufA -> out
}

// round 7
// speedup vs baseline: 1.6240x; 1.0849x over previous
#include <cuda_runtime.h>
#include <cuda_fp16.h>

#define NN 100000
#define NE 1000000
#define D  64
#define HS 68              // smem h-row stride (floats)
#define SCAN_BS 1024
#define NBLK 98            // ceil(NN/1024)

// ---------------- static scratch ----------------
__device__ __half2 g_bufA[NN * (D / 2)];   // fp16 feature buffer (ping)
__device__ __half2 g_bufB[NN * (D / 2)];   // fp16 feature buffer (pong)
__device__ float g_out_norm[NN];
__device__ float g_in_norm[NN];
__device__ int   g_deg_out[NN];
__device__ int   g_deg_in[NN];
__device__ int   g_row_start[NN];
__device__ int   g_fill[NN];
__device__ int   g_src_sorted[NE];
__device__ int   g_bsum[NBLK];

// ---------------- helpers ----------------
__device__ __forceinline__ unsigned long long pk2(float lo, float hi) {
    unsigned long long r;
    asm("mov.b64 %0, {%1,%2};" : "=l"(r) : "f"(lo), "f"(hi));
    return r;
}
__device__ __forceinline__ void fma2(unsigned long long& d,
                                     unsigned long long a, unsigned long long b) {
    asm("fma.rn.f32x2 %0, %1, %2, %0;" : "+l"(d) : "l"(a), "l"(b));
}
__device__ __forceinline__ float2 upk2(unsigned long long v) {
    float2 f;
    asm("mov.b64 {%0,%1}, %2;" : "=f"(f.x), "=f"(f.y) : "l"(v));
    return f;
}
__device__ __forceinline__ float2 h2f(unsigned int u) {
    float2 f;
    asm("{\n\t"
        ".reg .f16 lo, hi;\n\t"
        "mov.b32 {lo, hi}, %2;\n\t"
        "cvt.f32.f16 %0, lo;\n\t"
        "cvt.f32.f16 %1, hi;\n\t"
        "}"
        : "=f"(f.x), "=f"(f.y) : "r"(u));
    return f;
}
__device__ __forceinline__ unsigned int f2h(float a, float b) {
    unsigned int u;
    asm("{\n\t"
        ".reg .f16 lo, hi;\n\t"
        "cvt.rn.f16.f32 lo, %1;\n\t"
        "cvt.rn.f16.f32 hi, %2;\n\t"
        "mov.b32 %0, {lo, hi};\n\t"
        "}"
        : "=r"(u) : "f"(a), "f"(b));
    return u;
}
__device__ __forceinline__ void addrow(float* acc, uint4 r) {
    float2 f;
    f = h2f(r.x); acc[0] += f.x; acc[1] += f.y;
    f = h2f(r.y); acc[2] += f.x; acc[3] += f.y;
    f = h2f(r.z); acc[4] += f.x; acc[5] += f.y;
    f = h2f(r.w); acc[6] += f.x; acc[7] += f.y;
}

// ---------------- setup kernels ----------------
__global__ void zero_deg_kernel() {
    int i = blockIdx.x * blockDim.x + threadIdx.x;
    if (i < NN) { g_deg_out[i] = 0; g_deg_in[i] = 0; }
}

__global__ void count_kernel(const int* __restrict__ src, const int* __restrict__ dst) {
    int e = blockIdx.x * blockDim.x + threadIdx.x;
    if (e < NE) {
        atomicAdd(&g_deg_out[src[e]], 1);
        atomicAdd(&g_deg_in[dst[e]], 1);
    }
}

// block-level scan of deg_in
__global__ void scan1_kernel() {
    __shared__ int sh[SCAN_BS];
    int t = threadIdx.x;
    int i = blockIdx.x * SCAN_BS + t;
    int v = (i < NN) ? g_deg_in[i] : 0;
    sh[t] = v;
    __syncthreads();
#pragma unroll
    for (int off = 1; off < SCAN_BS; off <<= 1) {
        int xv = (t >= off) ? sh[t - off] : 0;
        __syncthreads();
        sh[t] += xv;
        __syncthreads();
    }
    if (i < NN) g_row_start[i] = sh[t] - v;
    if (t == SCAN_BS - 1) g_bsum[blockIdx.x] = sh[t];
}

// finalize: each block re-scans the 98 block sums in smem (replaces scan2 launch),
// adds the offset, writes row_start + fill cursors + both degree norms.
__global__ void scan3_kernel() {
    __shared__ int s[128];
    int t = threadIdx.x;
    if (t < 128) s[t] = (t < NBLK) ? g_bsum[t] : 0;
    __syncthreads();
#pragma unroll
    for (int off = 1; off < 128; off <<= 1) {
        int xv = (t >= off && t < 128) ? s[t - off] : 0;
        __syncthreads();
        if (t < 128) s[t] += xv;      // inclusive scan
        __syncthreads();
    }
    int i = blockIdx.x * blockDim.x + t;
    if (i < NN) {
        int blk = i >> 10;
        int boff = (blk == 0) ? 0 : s[blk - 1];
        int rs = g_row_start[i] + boff;
        g_row_start[i] = rs;
        g_fill[i] = rs;
        int dout = g_deg_out[i]; if (dout < 1) dout = 1;
        int din  = g_deg_in[i];  if (din  < 1) din  = 1;
        g_out_norm[i] = rsqrtf((float)dout);
        g_in_norm[i]  = rsqrtf((float)din);
    }
}

__global__ void fill_kernel(const int* __restrict__ src, const int* __restrict__ dst) {
    int e = blockIdx.x * blockDim.x + threadIdx.x;
    if (e < NE) {
        int p = atomicAdd(&g_fill[dst[e]], 1);
        g_src_sorted[p] = src[e];
    }
}

// xs = fp16( x * out_norm[row] ) into bufA
__global__ void prescale_kernel(const float4* __restrict__ x) {
    int i = blockIdx.x * blockDim.x + threadIdx.x;
    if (i < NN * (D / 4)) {
        float s = g_out_norm[i >> 4];
        float4 v = __ldg(&x[i]);
        uint2 st;
        st.x = f2h(v.x * s, v.y * s);
        st.y = f2h(v.z * s, v.w * s);
        reinterpret_cast<uint2*>(g_bufA)[i] = st;
    }
}

// ---------------- fused gather + GEMM layer ----------------
// 32 nodes/block, 256 threads.
// Phase 1: 8 lanes/node, each lane owns one 16B slice (uint4 = 8 halves) of the
//          128B fp16 row; streams all in-edges, fp32 accumulate, x4 unroll.
// Phase 2: all 8 warps GEMM, 4 nodes/warp, FFMA2.
__global__ void __launch_bounds__(256) layer_kernel(
        int in_sel, float* __restrict__ out_ext, int out_sel,
        const float* __restrict__ W, const float* __restrict__ b,
        int relu, int scale_out) {
    __shared__ float sW[D * D];      // 16KB
    __shared__ float sh[32 * HS];    // 8.7KB
    __shared__ float sb[D];

    int tid = threadIdx.x;
    for (int i = tid; i < D * D; i += 256) sW[i] = W[i];
    if (tid < D) sb[tid] = b[tid];

    const __half2* in = in_sel ? g_bufB : g_bufA;
    __half2* out_h16 = out_sel ? g_bufB : g_bufA;

    // ---- phase 1: aggregation ----
    int g  = tid >> 3;          // node slot 0..31
    int c8 = tid & 7;           // 16B column slice
    int node = blockIdx.x * 32 + g;   // NN % 32 == 0: always valid

    float acc[8];
#pragma unroll
    for (int j = 0; j < 8; j++) acc[j] = 0.f;

    {
        const uint4* inp = reinterpret_cast<const uint4*>(in);  // 8 uint4 per row
        int e = g_row_start[node];
        int eend = e + g_deg_in[node];
        for (; e + 3 < eend; e += 4) {
            int s0 = g_src_sorted[e];
            int s1 = g_src_sorted[e + 1];
            int s2 = g_src_sorted[e + 2];
            int s3 = g_src_sorted[e + 3];
            uint4 r0 = __ldg(&inp[s0 * 8 + c8]);
            uint4 r1 = __ldg(&inp[s1 * 8 + c8]);
            uint4 r2 = __ldg(&inp[s2 * 8 + c8]);
            uint4 r3 = __ldg(&inp[s3 * 8 + c8]);
            addrow(acc, r0);
            addrow(acc, r1);
            addrow(acc, r2);
            addrow(acc, r3);
        }
        for (; e < eend; e++) {
            int s0 = g_src_sorted[e];
            uint4 r0 = __ldg(&inp[s0 * 8 + c8]);
            addrow(acc, r0);
        }
        float nrm = g_in_norm[node];
        float* dstp = &sh[g * HS + c8 * 8];
        *reinterpret_cast<float4*>(dstp) =
            make_float4(acc[0] * nrm, acc[1] * nrm, acc[2] * nrm, acc[3] * nrm);
        *reinterpret_cast<float4*>(dstp + 4) =
            make_float4(acc[4] * nrm, acc[5] * nrm, acc[6] * nrm, acc[7] * nrm);
    }
    __syncthreads();

    // ---- phase 2: GEMM (8 warps x 4 nodes, FFMA2) ----
    {
        int w = tid >> 5;
        int lane = tid & 31;
        int r0 = lane >> 4;       // 0/1
        int c2 = lane & 15;       // output col quad
        unsigned long long acc01[2], acc23[2];
#pragma unroll
        for (int m = 0; m < 2; m++) { acc01[m] = 0ull; acc23[m] = 0ull; }

#pragma unroll
        for (int kb = 0; kb < 16; kb++) {
            float4 a4[2];
#pragma unroll
            for (int m = 0; m < 2; m++)
                a4[m] = *reinterpret_cast<const float4*>(
                    &sh[(w * 4 + r0 + 2 * m) * HS + kb * 4]);
#pragma unroll
            for (int q = 0; q < 4; q++) {
                int k = kb * 4 + q;
                unsigned long long w01 =
                    *reinterpret_cast<const unsigned long long*>(&sW[k * D + c2 * 4]);
                unsigned long long w23 =
                    *reinterpret_cast<const unsigned long long*>(&sW[k * D + c2 * 4 + 2]);
#pragma unroll
                for (int m = 0; m < 2; m++) {
                    float a = (q == 0) ? a4[m].x : (q == 1) ? a4[m].y
                             : (q == 2) ? a4[m].z : a4[m].w;
                    unsigned long long aa = pk2(a, a);
                    fma2(acc01[m], aa, w01);
                    fma2(acc23[m], aa, w23);
                }
            }
        }
        float b0 = sb[c2 * 4 + 0], b1 = sb[c2 * 4 + 1];
        float b2 = sb[c2 * 4 + 2], b3 = sb[c2 * 4 + 3];
#pragma unroll
        for (int m = 0; m < 2; m++) {
            int nd = blockIdx.x * 32 + w * 4 + r0 + 2 * m;
            float2 v01 = upk2(acc01[m]);
            float2 v23 = upk2(acc23[m]);
            float o0 = v01.x + b0, o1 = v01.y + b1;
            float o2 = v23.x + b2, o3 = v23.y + b3;
            if (relu) {
                o0 = fmaxf(o0, 0.f); o1 = fmaxf(o1, 0.f);
                o2 = fmaxf(o2, 0.f); o3 = fmaxf(o3, 0.f);
            }
            if (scale_out) {
                float on = g_out_norm[nd];
                o0 *= on; o1 *= on; o2 *= on; o3 *= on;
            }
            if (out_ext) {
                reinterpret_cast<float4*>(out_ext)[nd * 16 + c2] =
                    make_float4(o0, o1, o2, o3);
            } else {
                uint2 st;
                st.x = f2h(o0, o1);
                st.y = f2h(o2, o3);
                reinterpret_cast<uint2*>(out_h16)[nd * 16 + c2] = st;
            }
        }
    }
}

// ---------------- launch ----------------
extern "C" void kernel_launch(void* const* d_in, const int* in_sizes, int n_in,
                              void* d_out, int out_size) {
    const float* x   = (const float*)d_in[0];
    const int*   src = (const int*)d_in[1];
    const int*   dst = (const int*)d_in[2];
    const float* W1  = (const float*)d_in[3];
    const float* b1  = (const float*)d_in[4];
    const float* W2  = (const float*)d_in[5];
    const float* b2  = (const float*)d_in[6];
    const float* W3  = (const float*)d_in[7];
    const float* b3  = (const float*)d_in[8];
    float* out = (float*)d_out;

    const int TB = 256;
    const int GN = (NN + TB - 1) / TB;
    const int GE = (NE + TB - 1) / TB;

    zero_deg_kernel<<<GN, TB>>>();
    count_kernel<<<GE, TB>>>(src, dst);
    scan1_kernel<<<NBLK, SCAN_BS>>>();
    scan3_kernel<<<GN, TB>>>();     // folds scan2 + norms + fill cursors
    fill_kernel<<<GE, TB>>>(src, dst);
    prescale_kernel<<<(NN * 16 + TB - 1) / TB, TB>>>(
        reinterpret_cast<const float4*>(x));

    const int GL = NN / 32;         // 3125, exact
    layer_kernel<<<GL, 256>>>(0, nullptr, 1, W1, b1, 1, 1);   // bufA -> bufB
    layer_kernel<<<GL, 256>>>(1, nullptr, 0, W2, b2, 1, 1);   // bufB -> bufA
    layer_kernel<<<GL, 256>>>(0, out, 0, W3, b3, 0, 0);       // bufA -> out
}